// round 13
// baseline (speedup 1.0000x reference)
#include <cuda_runtime.h>
#include <cuda_fp16.h>
#include <cstdint>

#define CB 2
#define CH 16
#define CS 2048
#define CD 128

constexpr int C_BH = CB * CH;   // 32
constexpr int C_NT = CS / 128;  // 16 B/E tiles along S (128-wide)
constexpr int C_ST = CS / 64;   // 32 score s-tiles (64 rows each)

// -------- device scratch (allocation-free per harness rules) --------
__device__ __half    g_x2h[(size_t)C_BH * CS * CD];
__device__ __half    g_x3h[(size_t)C_BH * CD * CS];  // x3 * recip[s], fp16 (written by score)
__device__ uint16_t  g_masku[(size_t)CS * CS];       // (mask*log2e+16)*2048, u16 fixed point
__device__ __half    g_E[(size_t)C_BH * CS * CS];    // unnormalized exp * 2^-10, fp16

#define LOG2E_F 1.4426950408889634f
#define MQ_ENC  2954.6394367894f
#define MQ_DEC  4.8828125e-4f
#define MQ_BIAS (-26.0f)
__device__ __forceinline__ float c_scale_log2e() { return 0.08838834764831843f * 1.4426950408889634f; }

// -------- helpers --------
__device__ __forceinline__ uint32_t smem_u32(const void* p) {
    return (uint32_t)__cvta_generic_to_shared(p);
}
__device__ __forceinline__ float ex2f(float x) { float y; asm("ex2.approx.ftz.f32 %0, %1;" : "=f"(y) : "f"(x)); return y; }

// swizzled offset in a [rows x 128 halves/u16] tile: 256B rows, 16B chunks (ch 0..15)
__device__ __forceinline__ uint32_t off(int row, int ch) {
    return (uint32_t)(row * 256 + ((ch ^ (row & 7)) << 4));
}
// swizzled offset in a [rows x 64 halves] tile: 128B rows, 16B chunks (ch 0..7)
__device__ __forceinline__ uint32_t offE(int row, int ch) {
    return (uint32_t)(row * 128 + ((ch ^ (row & 7)) << 4));
}

__device__ __forceinline__ void lds_x4(uint32_t a[4], uint32_t addr) {
    asm volatile("ldmatrix.sync.aligned.m8n8.x4.shared.b16 {%0,%1,%2,%3}, [%4];"
                 : "=r"(a[0]), "=r"(a[1]), "=r"(a[2]), "=r"(a[3]) : "r"(addr));
}
__device__ __forceinline__ void lds_x4_t(uint32_t a[4], uint32_t addr) {
    asm volatile("ldmatrix.sync.aligned.m8n8.x4.trans.shared.b16 {%0,%1,%2,%3}, [%4];"
                 : "=r"(a[0]), "=r"(a[1]), "=r"(a[2]), "=r"(a[3]) : "r"(addr));
}
__device__ __forceinline__ void mma16816(float c[4], const uint32_t a[4], uint32_t b0, uint32_t b1) {
    asm volatile("mma.sync.aligned.m16n8k16.row.col.f32.f16.f16.f32 "
                 "{%0,%1,%2,%3}, {%4,%5,%6,%7}, {%8,%9}, {%0,%1,%2,%3};"
                 : "+f"(c[0]), "+f"(c[1]), "+f"(c[2]), "+f"(c[3])
                 : "r"(a[0]), "r"(a[1]), "r"(a[2]), "r"(a[3]), "r"(b0), "r"(b1));
}
__device__ __forceinline__ void cpa16(uint32_t saddr, const void* g) {
    asm volatile("cp.async.cg.shared.global [%0], [%1], 16;" :: "r"(saddr), "l"(g));
}
#define CP_COMMIT() asm volatile("cp.async.commit_group;" ::: "memory")
#define CP_WAIT0()  asm volatile("cp.async.wait_group 0;" ::: "memory")

// ================= kernel 1: fp16 convert (x2) + mask -> u16 fixed point =================
__global__ void __launch_bounds__(256) convert_kernel(const float* __restrict__ x2,
                                                      const float* __restrict__ mask) {
    constexpr size_t SEG = (size_t)C_BH * CS * CD / 4;   // 2097152
    constexpr size_t SEGM = (size_t)CS * CS / 4;         // 1048576
    size_t t = (size_t)blockIdx.x * blockDim.x + threadIdx.x;
    if (t < SEG) {
        float4 v = reinterpret_cast<const float4*>(x2)[t];
        __half2 h0 = __floats2half2_rn(v.x, v.y), h1 = __floats2half2_rn(v.z, v.w);
        uint2 u = { *(uint32_t*)&h0, *(uint32_t*)&h1 };
        reinterpret_cast<uint2*>(g_x2h)[t] = u;
    } else if (t < SEG + SEGM) {
        t -= SEG;
        float4 v = reinterpret_cast<const float4*>(mask)[t];
        float q0 = fminf(fmaxf(fmaf(v.x, MQ_ENC, 32768.f), 0.f), 65535.f);
        float q1 = fminf(fmaxf(fmaf(v.y, MQ_ENC, 32768.f), 0.f), 65535.f);
        float q2 = fminf(fmaxf(fmaf(v.z, MQ_ENC, 32768.f), 0.f), 65535.f);
        float q3 = fminf(fmaxf(fmaf(v.w, MQ_ENC, 32768.f), 0.f), 65535.f);
        uint32_t w0 = __float2uint_rn(q0) | (__float2uint_rn(q1) << 16);
        uint32_t w1 = __float2uint_rn(q2) | (__float2uint_rn(q3) << 16);
        uint2 u = { w0, w1 };
        reinterpret_cast<uint2*>(g_masku)[t] = u;
    }
}

// ================= kernel 2: scores -> exp -> E + rowsum + x3 scaling =================
// CTA tile: 64(s) x 128(kc per iter, sweep 16). bh = bid&31 (s-major), sbase = (bid>>5)*64.
// Warp layout: 2m x 4n, warp tile 32x32. 32 accums/thread.
// Mask: direct u16 LDG into REGISTERS, issued at top of MMA phase (L2 latency hidden
// under HMMA). No mask SMEM, no 3rd barrier. 2 syncs + 1 wait per iteration.
// SMEM: A 16KB @0 | B 32KB @16K | rowsum 256B @48K  (49408 B, 3 CTA/SM)
__global__ void __launch_bounds__(256, 3) score_kernel(const float* __restrict__ x1,
                                                       const float* __restrict__ x3) {
    extern __shared__ char smem[];
    const int tid = threadIdx.x, lane = tid & 31, wid = tid >> 5;
    const int wm = wid & 1, wn = wid >> 1;
    const int bh = blockIdx.x & 31;
    const int sbase = (blockIdx.x >> 5) * 64;

    const uint32_t sbA = smem_u32(smem);
    const uint32_t sbB = sbA + 16384;
    float* srs = reinterpret_cast<float*>(smem + 49152);

    if (tid < 64) srs[tid] = 0.f;

    // prologue: B(0)
    const __half* gB0 = g_x2h + (size_t)bh * CS * CD;
#pragma unroll
    for (int i = 0; i < 8; i++) {
        int idx = tid + 256 * i, row = idx >> 4, ch = idx & 15;
        cpa16(sbB + off(row, ch), gB0 + row * CD + ch * 8);
    }
    CP_COMMIT();

    // stage A: x1 fp32 -> fp16 inline (64 rows x 128 cols)
    const float* gA = x1 + ((size_t)(bh * CS + sbase)) * CD;
#pragma unroll
    for (int i = 0; i < 4; i++) {
        int idx = tid + 256 * i, row = idx >> 4, ch = idx & 15;
        const float4* s = reinterpret_cast<const float4*>(gA + row * CD + ch * 8);
        float4 v0 = s[0], v1 = s[1];
        __half2 h0 = __floats2half2_rn(v0.x, v0.y), h1 = __floats2half2_rn(v0.z, v0.w);
        __half2 h2 = __floats2half2_rn(v1.x, v1.y), h3 = __floats2half2_rn(v1.z, v1.w);
        uint4 u = { *(uint32_t*)&h0, *(uint32_t*)&h1, *(uint32_t*)&h2, *(uint32_t*)&h3 };
        *reinterpret_cast<uint4*>(smem + off(row, ch)) = u;
    }

    const float c1 = c_scale_log2e();
    float rs0 = 0.f, rs1 = 0.f, rs2 = 0.f, rs3 = 0.f;

    const int arow = wm * 32 + (lane & 15);
    const int brow = wn * 32 + (lane & 7) + ((lane & 16) >> 1);
    const int ahb = lane >> 4;
    const int bhb = (lane >> 3) & 1;

    // this thread's mask base rows (fixed across iterations)
    const int er0 = wm * 32 + (lane >> 2);          // mt=0 row
    const int ecol = wn * 32 + (lane & 3) * 2;      // base col within 128-tile
    const uint16_t* mbase0 = g_masku + (size_t)(sbase + er0) * CS + ecol;   // rows er0, er0+8
    const uint16_t* mbase2 = mbase0 + (size_t)16 * CS;                      // rows er0+16, er0+24

    for (int kct = 0; kct < C_NT; kct++) {
        CP_WAIT0();          // B(kct) ready (only B outstanding)
        __syncthreads();

        // issue this thread's 16 mask loads NOW -- they complete under the MMA phase
        const int gcb = kct * 128;
        uint32_t mw[4][4];   // [rowgroup: er0, er0+8, er0+16, er0+24][nt]
#pragma unroll
        for (int nt = 0; nt < 4; nt++) {
            mw[0][nt] = __ldg(reinterpret_cast<const uint32_t*>(mbase0 + gcb + nt * 8));
            mw[1][nt] = __ldg(reinterpret_cast<const uint32_t*>(mbase0 + 8 * CS + gcb + nt * 8));
            mw[2][nt] = __ldg(reinterpret_cast<const uint32_t*>(mbase2 + gcb + nt * 8));
            mw[3][nt] = __ldg(reinterpret_cast<const uint32_t*>(mbase2 + 8 * CS + gcb + nt * 8));
        }

        float c[2][4][4];
#pragma unroll
        for (int mt = 0; mt < 2; mt++)
#pragma unroll
            for (int nt = 0; nt < 4; nt++)
#pragma unroll
                for (int q = 0; q < 4; q++) c[mt][nt][q] = 0.f;

#pragma unroll
        for (int ks = 0; ks < 8; ks++) {
            uint32_t a[2][4], b[2][4];
#pragma unroll
            for (int mt = 0; mt < 2; mt++)
                lds_x4(a[mt], sbA + off(arow + mt * 16, ks * 2 + ahb));
#pragma unroll
            for (int ntb = 0; ntb < 2; ntb++)
                lds_x4(b[ntb], sbB + off(brow + ntb * 16, ks * 2 + bhb));
#pragma unroll
            for (int mt = 0; mt < 2; mt++)
#pragma unroll
                for (int ntb = 0; ntb < 2; ntb++) {
                    mma16816(c[mt][ntb * 2 + 0], a[mt], b[ntb][0], b[ntb][1]);
                    mma16816(c[mt][ntb * 2 + 1], a[mt], b[ntb][2], b[ntb][3]);
                }
        }
        __syncthreads();     // B consumed by all warps -> safe to refill

        if (kct + 1 < C_NT) {
            const __half* gB = g_x2h + ((size_t)(bh * CS + (kct + 1) * 128)) * CD;
#pragma unroll
            for (int i = 0; i < 8; i++) {
                int idx = tid + 256 * i, row = idx >> 4, ch = idx & 15;
                cpa16(sbB + off(row, ch), gB + row * CD + ch * 8);
            }
            CP_COMMIT();
        }

        // epilogue: decode mask regs -> exp -> E store + rowsum (no SMEM, no wait)
#pragma unroll
        for (int mt = 0; mt < 2; mt++) {
            const int r0 = er0 + mt * 16;
            __half* ep0 = g_E + ((size_t)(bh * CS + sbase + r0)) * CS + gcb;
            __half* ep1 = ep0 + 8 * CS;
#pragma unroll
            for (int nt = 0; nt < 4; nt++) {
                const int col = ecol + nt * 8;
                uint32_t mw0 = mw[mt * 2 + 0][nt];
                uint32_t mw1 = mw[mt * 2 + 1][nt];
                float m00 = fmaf((float)(mw0 & 0xffff), MQ_DEC, MQ_BIAS);
                float m01 = fmaf((float)(mw0 >> 16),    MQ_DEC, MQ_BIAS);
                float m10 = fmaf((float)(mw1 & 0xffff), MQ_DEC, MQ_BIAS);
                float m11 = fmaf((float)(mw1 >> 16),    MQ_DEC, MQ_BIAS);
                float e00 = ex2f(fmaf(c[mt][nt][0], c1, m00));
                float e01 = ex2f(fmaf(c[mt][nt][1], c1, m01));
                float e10 = ex2f(fmaf(c[mt][nt][2], c1, m10));
                float e11 = ex2f(fmaf(c[mt][nt][3], c1, m11));
                *reinterpret_cast<__half2*>(ep0 + col) = __floats2half2_rn(e00, e01);
                *reinterpret_cast<__half2*>(ep1 + col) = __floats2half2_rn(e10, e11);
                if (mt == 0) { rs0 += e00 + e01; rs1 += e10 + e11; }
                else         { rs2 += e00 + e01; rs3 += e10 + e11; }
            }
        }
    }

    rs0 += __shfl_xor_sync(~0u, rs0, 1); rs0 += __shfl_xor_sync(~0u, rs0, 2);
    rs1 += __shfl_xor_sync(~0u, rs1, 1); rs1 += __shfl_xor_sync(~0u, rs1, 2);
    rs2 += __shfl_xor_sync(~0u, rs2, 1); rs2 += __shfl_xor_sync(~0u, rs2, 2);
    rs3 += __shfl_xor_sync(~0u, rs3, 1); rs3 += __shfl_xor_sync(~0u, rs3, 2);
    if ((lane & 3) == 0) {
        int r = wm * 32 + (lane >> 2);
        atomicAdd(&srs[r],      rs0);
        atomicAdd(&srs[r + 8],  rs1);
        atomicAdd(&srs[r + 16], rs2);
        atomicAdd(&srs[r + 24], rs3);
    }
    __syncthreads();
    if (tid < 64) srs[tid] = 1.0f / srs[tid];
    __syncthreads();

    // tail: x3h[bh][d][sbase+j] = fp16(x3 * recip[j]), 128 rows x 64 cols
    const float* gx3f = x3 + (size_t)bh * CD * CS + sbase;
    __half* gx3h = g_x3h + (size_t)bh * CD * CS + sbase;
#pragma unroll
    for (int i = 0; i < 8; i++) {
        int idx = tid + 256 * i, row = idx >> 4, ch = idx & 15;   // ch: float4 chunk (4 cols)
        float4 v = __ldg(reinterpret_cast<const float4*>(gx3f + (size_t)row * CS + ch * 4));
        float4 r = *reinterpret_cast<const float4*>(&srs[ch * 4]);
        __half2 h0 = __floats2half2_rn(v.x * r.x, v.y * r.y);
        __half2 h1 = __floats2half2_rn(v.z * r.z, v.w * r.w);
        uint2 u = { *(uint32_t*)&h0, *(uint32_t*)&h1 };
        *reinterpret_cast<uint2*>(gx3h + (size_t)row * CS + ch * 4) = u;
    }
}

// ================= kernel 3: out = x3' @ E  (output-stationary) =================
// CTA tile: 128(d) x 64(kc). bh reversed (L2-hot E first). kcbase = (bid&31)*64.
// Warp layout: 4m x 2n, warp tile 32x32. 32 accums/thread.
// SMEM: A 32KB @0 | E0 16KB @32K | E1 16KB @48K  (64KB, 3 CTA/SM)
__global__ void __launch_bounds__(256, 3) pv_kernel(float* __restrict__ out) {
    extern __shared__ char smem[];
    const int tid = threadIdx.x, lane = tid & 31, wid = tid >> 5;
    const int wm = wid & 3, wn = wid >> 2;
    const int bh = (C_BH - 1) - (blockIdx.x >> 5);
    const int kcbase = (blockIdx.x & 31) * 64;

    const uint32_t sbA  = smem_u32(smem);
    const uint32_t sbE0 = sbA + 32768;
    const uint32_t sbE1 = sbA + 49152;

    const __half* gA3 = g_x3h + (size_t)bh * CD * CS;
    const __half* gEb = g_E + ((size_t)bh * CS) * CS + kcbase;

    // prologue: E(0), A(0)
#pragma unroll
    for (int i = 0; i < 4; i++) {
        int idx = tid + 256 * i, row = idx >> 3, ch = idx & 7;
        cpa16(sbE0 + offE(row, ch), gEb + (size_t)row * CS + ch * 8);
    }
    CP_COMMIT();
#pragma unroll
    for (int i = 0; i < 8; i++) {
        int idx = tid + 256 * i, row = idx >> 4, ch = idx & 15;
        cpa16(sbA + off(row, ch), gA3 + (size_t)row * CS + ch * 8);
    }
    CP_COMMIT();

    float c[2][4][4];
#pragma unroll
    for (int mt = 0; mt < 2; mt++)
#pragma unroll
        for (int nt = 0; nt < 4; nt++)
#pragma unroll
            for (int q = 0; q < 4; q++) c[mt][nt][q] = 0.f;

    const int arow = wm * 32 + (lane & 15);
    const int ahb = lane >> 4;
    const int btrow = lane & 15;
    const int btch_base = wn * 4 + (lane >> 4);

    for (int st = 0; st < C_NT; st++) {
        const uint32_t sbE = (st & 1) ? sbE1 : sbE0;

        CP_WAIT0();
        __syncthreads();

        // prefetch E(st+1) into other buffer; hides under MMA below
        if (st + 1 < C_NT) {
            const __half* gE = gEb + (size_t)(st + 1) * 128 * CS;
            uint32_t dst = ((st + 1) & 1) ? sbE1 : sbE0;
#pragma unroll
            for (int i = 0; i < 4; i++) {
                int idx = tid + 256 * i, row = idx >> 3, ch = idx & 7;
                cpa16(dst + offE(row, ch), gE + (size_t)row * CS + ch * 8);
            }
            CP_COMMIT();
        }

#pragma unroll
        for (int ks = 0; ks < 8; ks++) {
            uint32_t a[2][4], b[2][4];
#pragma unroll
            for (int mt = 0; mt < 2; mt++)
                lds_x4(a[mt], sbA + off(arow + mt * 16, ks * 2 + ahb));
#pragma unroll
            for (int ntb = 0; ntb < 2; ntb++)
                lds_x4_t(b[ntb], sbE + offE(ks * 16 + btrow, btch_base + ntb * 2));
#pragma unroll
            for (int mt = 0; mt < 2; mt++)
#pragma unroll
                for (int ntb = 0; ntb < 2; ntb++) {
                    mma16816(c[mt][ntb * 2 + 0], a[mt], b[ntb][0], b[ntb][1]);
                    mma16816(c[mt][ntb * 2 + 1], a[mt], b[ntb][2], b[ntb][3]);
                }
        }
        __syncthreads();
        // refill A(st+1) (L2-resident x3h; lands before next wait)
        if (st + 1 < C_NT) {
#pragma unroll
            for (int i = 0; i < 8; i++) {
                int idx = tid + 256 * i, row = idx >> 4, ch = idx & 15;
                cpa16(sbA + off(row, ch), gA3 + (size_t)row * CS + (st + 1) * 128 + ch * 8);
            }
            CP_COMMIT();
        }
    }

    // epilogue: fp32 store out[bh][d][kc]
#pragma unroll
    for (int mt = 0; mt < 2; mt++) {
        const int d0 = wm * 32 + mt * 16 + (lane >> 2);
#pragma unroll
        for (int nt = 0; nt < 4; nt++) {
            const int col = kcbase + wn * 32 + nt * 8 + (lane & 3) * 2;
            float2 v0 = make_float2(c[mt][nt][0], c[mt][nt][1]);
            float2 v1 = make_float2(c[mt][nt][2], c[mt][nt][3]);
            *reinterpret_cast<float2*>(out + ((size_t)(bh * CD + d0)) * CS + col) = v0;
            *reinterpret_cast<float2*>(out + ((size_t)(bh * CD + d0 + 8)) * CS + col) = v1;
        }
    }
}

// ================= launch =================
extern "C" void kernel_launch(void* const* d_in, const int* in_sizes, int n_in,
                              void* d_out, int out_size) {
    (void)in_sizes; (void)n_in; (void)out_size;
    const float* x1   = (const float*)d_in[0];
    const float* x2   = (const float*)d_in[1];
    const float* x3   = (const float*)d_in[2];
    const float* mask = (const float*)d_in[3];
    float* out = (float*)d_out;

    cudaFuncSetAttribute(score_kernel, cudaFuncAttributeMaxDynamicSharedMemorySize, 49408);
    cudaFuncSetAttribute(pv_kernel,    cudaFuncAttributeMaxDynamicSharedMemorySize, 65536);

    constexpr size_t TOT4 = ((size_t)C_BH * CS * CD / 4) + (size_t)CS * CS / 4;
    convert_kernel<<<(int)((TOT4 + 255) / 256), 256>>>(x2, mask);
    score_kernel<<<C_BH * C_ST, 256, 49408>>>(x1, x3);
    pv_kernel<<<C_BH * C_ST, 256, 65536>>>(out);
}

// round 14
// speedup vs baseline: 1.0024x; 1.0024x over previous
#include <cuda_runtime.h>
#include <cuda_fp16.h>
#include <cstdint>

#define CB 2
#define CH 16
#define CS 2048
#define CD 128

constexpr int C_BH = CB * CH;   // 32
constexpr int C_NT = CS / 128;  // 16 B/E tiles along S (128-wide)
constexpr int N_SCORE = C_BH * 32;        // 1024 score items (64-row s-tiles)
constexpr int N_ITEMS = 2 * N_SCORE;      // 2048
constexpr int GRID_P  = 456;              // 3 per SM x 152 SMs (safe on 148 too)

// -------- device scratch (allocation-free per harness rules) --------
__device__ __half    g_x2h[(size_t)C_BH * CS * CD];
__device__ __half    g_x3h[(size_t)C_BH * CD * CS];  // x3 * recip[s], fp16 (score tail)
__device__ uint16_t  g_masku[(size_t)CS * CS];       // (mask*log2e+16)*2048, u16 fixed point
__device__ __half    g_E[(size_t)C_BH * CS * CS];    // unnormalized exp * 2^-10, fp16
__device__ int       g_next;                          // monotonic work queue head
__device__ int       g_done[C_BH];                    // per-bh completed score items (of 32)

#define LOG2E_F 1.4426950408889634f
#define MQ_ENC  2954.6394367894f
#define MQ_DEC  4.8828125e-4f
#define MQ_BIAS (-26.0f)
__device__ __forceinline__ float c_scale_log2e() { return 0.08838834764831843f * 1.4426950408889634f; }

// -------- helpers --------
__device__ __forceinline__ uint32_t smem_u32(const void* p) {
    return (uint32_t)__cvta_generic_to_shared(p);
}
__device__ __forceinline__ float ex2f(float x) { float y; asm("ex2.approx.ftz.f32 %0, %1;" : "=f"(y) : "f"(x)); return y; }

// swizzled offset in a [rows x 128 halves/u16] tile: 256B rows, 16B chunks (ch 0..15)
__device__ __forceinline__ uint32_t off(int row, int ch) {
    return (uint32_t)(row * 256 + ((ch ^ (row & 7)) << 4));
}
// byte offset of 2B element [row][col] in the 256B-row layout
__device__ __forceinline__ uint32_t moff(int row, int col) {
    return (uint32_t)(row * 256 + ((((col >> 3) ^ (row & 7)) << 4) | ((col & 7) << 1)));
}
// swizzled offset in a [rows x 64 halves] tile: 128B rows, 16B chunks (ch 0..7)
__device__ __forceinline__ uint32_t offE(int row, int ch) {
    return (uint32_t)(row * 128 + ((ch ^ (row & 7)) << 4));
}

__device__ __forceinline__ void lds_x4(uint32_t a[4], uint32_t addr) {
    asm volatile("ldmatrix.sync.aligned.m8n8.x4.shared.b16 {%0,%1,%2,%3}, [%4];"
                 : "=r"(a[0]), "=r"(a[1]), "=r"(a[2]), "=r"(a[3]) : "r"(addr));
}
__device__ __forceinline__ void lds_x4_t(uint32_t a[4], uint32_t addr) {
    asm volatile("ldmatrix.sync.aligned.m8n8.x4.trans.shared.b16 {%0,%1,%2,%3}, [%4];"
                 : "=r"(a[0]), "=r"(a[1]), "=r"(a[2]), "=r"(a[3]) : "r"(addr));
}
__device__ __forceinline__ void mma16816(float c[4], const uint32_t a[4], uint32_t b0, uint32_t b1) {
    asm volatile("mma.sync.aligned.m16n8k16.row.col.f32.f16.f16.f32 "
                 "{%0,%1,%2,%3}, {%4,%5,%6,%7}, {%8,%9}, {%0,%1,%2,%3};"
                 : "+f"(c[0]), "+f"(c[1]), "+f"(c[2]), "+f"(c[3])
                 : "r"(a[0]), "r"(a[1]), "r"(a[2]), "r"(a[3]), "r"(b0), "r"(b1));
}
__device__ __forceinline__ void cpa16(uint32_t saddr, const void* g) {
    asm volatile("cp.async.cg.shared.global [%0], [%1], 16;" :: "r"(saddr), "l"(g));
}
#define CP_COMMIT() asm volatile("cp.async.commit_group;" ::: "memory")
#define CP_WAIT0()  asm volatile("cp.async.wait_group 0;" ::: "memory")
#define CP_WAIT1()  asm volatile("cp.async.wait_group 1;" ::: "memory")

// ================= kernel 1: convert + queue/counter reset =================
__global__ void __launch_bounds__(256) convert_kernel(const float* __restrict__ x2,
                                                      const float* __restrict__ mask) {
    if (blockIdx.x == 0 && threadIdx.x < C_BH + 1) {
        if (threadIdx.x == C_BH) g_next = 0;
        else g_done[threadIdx.x] = 0;
    }
    constexpr size_t SEG = (size_t)C_BH * CS * CD / 4;   // 2097152
    constexpr size_t SEGM = (size_t)CS * CS / 4;         // 1048576
    size_t t = (size_t)blockIdx.x * blockDim.x + threadIdx.x;
    if (t < SEG) {
        float4 v = reinterpret_cast<const float4*>(x2)[t];
        __half2 h0 = __floats2half2_rn(v.x, v.y), h1 = __floats2half2_rn(v.z, v.w);
        uint2 u = { *(uint32_t*)&h0, *(uint32_t*)&h1 };
        reinterpret_cast<uint2*>(g_x2h)[t] = u;
    } else if (t < SEG + SEGM) {
        t -= SEG;
        float4 v = reinterpret_cast<const float4*>(mask)[t];
        float q0 = fminf(fmaxf(fmaf(v.x, MQ_ENC, 32768.f), 0.f), 65535.f);
        float q1 = fminf(fmaxf(fmaf(v.y, MQ_ENC, 32768.f), 0.f), 65535.f);
        float q2 = fminf(fmaxf(fmaf(v.z, MQ_ENC, 32768.f), 0.f), 65535.f);
        float q3 = fminf(fmaxf(fmaf(v.w, MQ_ENC, 32768.f), 0.f), 65535.f);
        uint32_t w0 = __float2uint_rn(q0) | (__float2uint_rn(q1) << 16);
        uint32_t w1 = __float2uint_rn(q2) | (__float2uint_rn(q3) << 16);
        uint2 u = { w0, w1 };
        reinterpret_cast<uint2*>(g_masku)[t] = u;
    }
}

// ================= score item body (R11 structure, bh-major) =================
// CTA tile: 64(s) x 128(kc per iter, sweep 16).
// SMEM: A 16KB @0 | B 32KB @16K | M(u16) 16KB @48K | rowsum 256B @64K
__device__ __forceinline__ void score_body(char* smem, int bh, int sbase,
                                           const float* __restrict__ x1,
                                           const float* __restrict__ x3) {
    const int tid = threadIdx.x, lane = tid & 31, wid = tid >> 5;
    const int wm = wid & 1, wn = wid >> 1;
    const uint32_t sbA = smem_u32(smem);
    const uint32_t sbB = sbA + 16384;
    const uint32_t sbM = sbA + 49152;
    char* smM = smem + 49152;
    float* srs = reinterpret_cast<float*>(smem + 65536);

    if (tid < 64) srs[tid] = 0.f;

    // prologue: B(0) group, then M(0) group
    const __half* gB0 = g_x2h + (size_t)bh * CS * CD;
#pragma unroll
    for (int i = 0; i < 8; i++) {
        int idx = tid + 256 * i, row = idx >> 4, ch = idx & 15;
        cpa16(sbB + off(row, ch), gB0 + row * CD + ch * 8);
    }
    CP_COMMIT();
    const uint16_t* gM = g_masku + (size_t)sbase * CS;
#pragma unroll
    for (int i = 0; i < 4; i++) {
        int idx = tid + 256 * i, row = idx >> 4, ch = idx & 15;
        cpa16(sbM + off(row, ch), gM + (size_t)row * CS + ch * 8);
    }
    CP_COMMIT();

    // stage A: x1 fp32 -> fp16 inline (64 rows x 128 cols)
    const float* gA = x1 + ((size_t)(bh * CS + sbase)) * CD;
#pragma unroll
    for (int i = 0; i < 4; i++) {
        int idx = tid + 256 * i, row = idx >> 4, ch = idx & 15;
        const float4* s = reinterpret_cast<const float4*>(gA + row * CD + ch * 8);
        float4 v0 = s[0], v1 = s[1];
        __half2 h0 = __floats2half2_rn(v0.x, v0.y), h1 = __floats2half2_rn(v0.z, v0.w);
        __half2 h2 = __floats2half2_rn(v1.x, v1.y), h3 = __floats2half2_rn(v1.z, v1.w);
        uint4 u = { *(uint32_t*)&h0, *(uint32_t*)&h1, *(uint32_t*)&h2, *(uint32_t*)&h3 };
        *reinterpret_cast<uint4*>(smem + off(row, ch)) = u;
    }

    const float c1 = c_scale_log2e();
    float rs0 = 0.f, rs1 = 0.f, rs2 = 0.f, rs3 = 0.f;

    const int arow = wm * 32 + (lane & 15);
    const int brow = wn * 32 + (lane & 7) + ((lane & 16) >> 1);
    const int ahb = lane >> 4;
    const int bhb = (lane >> 3) & 1;

    for (int kct = 0; kct < C_NT; kct++) {
        CP_WAIT1();          // B(kct) ready; M(kct) in flight under MMA
        __syncthreads();

        float c[2][4][4];
#pragma unroll
        for (int mt = 0; mt < 2; mt++)
#pragma unroll
            for (int nt = 0; nt < 4; nt++)
#pragma unroll
                for (int q = 0; q < 4; q++) c[mt][nt][q] = 0.f;

#pragma unroll
        for (int ks = 0; ks < 8; ks++) {
            uint32_t a[2][4], b[2][4];
#pragma unroll
            for (int mt = 0; mt < 2; mt++)
                lds_x4(a[mt], sbA + off(arow + mt * 16, ks * 2 + ahb));
#pragma unroll
            for (int ntb = 0; ntb < 2; ntb++)
                lds_x4(b[ntb], sbB + off(brow + ntb * 16, ks * 2 + bhb));
#pragma unroll
            for (int mt = 0; mt < 2; mt++)
#pragma unroll
                for (int ntb = 0; ntb < 2; ntb++) {
                    mma16816(c[mt][ntb * 2 + 0], a[mt], b[ntb][0], b[ntb][1]);
                    mma16816(c[mt][ntb * 2 + 1], a[mt], b[ntb][2], b[ntb][3]);
                }
        }
        __syncthreads();
        if (kct + 1 < C_NT) {
            const __half* gB = g_x2h + ((size_t)(bh * CS + (kct + 1) * 128)) * CD;
#pragma unroll
            for (int i = 0; i < 8; i++) {
                int idx = tid + 256 * i, row = idx >> 4, ch = idx & 15;
                cpa16(sbB + off(row, ch), gB + row * CD + ch * 8);
            }
            CP_COMMIT();
            CP_WAIT1();      // M(kct) ready; B(kct+1) stays in flight
        } else {
            CP_WAIT0();
        }
        __syncthreads();

        // epilogue: u16 mask from SMEM -> exp -> E store (write-back, L2-hot for pv) + rowsum
        const int gcb = kct * 128;
#pragma unroll
        for (int mt = 0; mt < 2; mt++) {
            const int r0 = wm * 32 + mt * 16 + (lane >> 2);
            __half* ep0 = g_E + ((size_t)(bh * CS + sbase + r0)) * CS + gcb;
            __half* ep1 = ep0 + 8 * CS;
#pragma unroll
            for (int nt = 0; nt < 4; nt++) {
                const int col = wn * 32 + nt * 8 + (lane & 3) * 2;
                uint32_t mw0 = *reinterpret_cast<const uint32_t*>(smM + moff(r0, col));
                uint32_t mw1 = *reinterpret_cast<const uint32_t*>(smM + moff(r0 + 8, col));
                float m00 = fmaf((float)(mw0 & 0xffff), MQ_DEC, MQ_BIAS);
                float m01 = fmaf((float)(mw0 >> 16),    MQ_DEC, MQ_BIAS);
                float m10 = fmaf((float)(mw1 & 0xffff), MQ_DEC, MQ_BIAS);
                float m11 = fmaf((float)(mw1 >> 16),    MQ_DEC, MQ_BIAS);
                float e00 = ex2f(fmaf(c[mt][nt][0], c1, m00));
                float e01 = ex2f(fmaf(c[mt][nt][1], c1, m01));
                float e10 = ex2f(fmaf(c[mt][nt][2], c1, m10));
                float e11 = ex2f(fmaf(c[mt][nt][3], c1, m11));
                *reinterpret_cast<__half2*>(ep0 + col) = __floats2half2_rn(e00, e01);
                *reinterpret_cast<__half2*>(ep1 + col) = __floats2half2_rn(e10, e11);
                if (mt == 0) { rs0 += e00 + e01; rs1 += e10 + e11; }
                else         { rs2 += e00 + e01; rs3 += e10 + e11; }
            }
        }
        __syncthreads();
        if (kct + 1 < C_NT) {
#pragma unroll
            for (int i = 0; i < 4; i++) {
                int idx = tid + 256 * i, row = idx >> 4, ch = idx & 15;
                cpa16(sbM + off(row, ch), gM + (size_t)row * CS + (kct + 1) * 128 + ch * 8);
            }
            CP_COMMIT();
        }
    }

    rs0 += __shfl_xor_sync(~0u, rs0, 1); rs0 += __shfl_xor_sync(~0u, rs0, 2);
    rs1 += __shfl_xor_sync(~0u, rs1, 1); rs1 += __shfl_xor_sync(~0u, rs1, 2);
    rs2 += __shfl_xor_sync(~0u, rs2, 1); rs2 += __shfl_xor_sync(~0u, rs2, 2);
    rs3 += __shfl_xor_sync(~0u, rs3, 1); rs3 += __shfl_xor_sync(~0u, rs3, 2);
    if ((lane & 3) == 0) {
        int r = wm * 32 + (lane >> 2);
        atomicAdd(&srs[r],      rs0);
        atomicAdd(&srs[r + 8],  rs1);
        atomicAdd(&srs[r + 16], rs2);
        atomicAdd(&srs[r + 24], rs3);
    }
    __syncthreads();
    if (tid < 64) srs[tid] = 1.0f / srs[tid];
    __syncthreads();

    // tail: x3h[bh][d][sbase+j] = fp16(x3 * recip[j]), 128 rows x 64 cols
    const float* gx3f = x3 + (size_t)bh * CD * CS + sbase;
    __half* gx3h = g_x3h + (size_t)bh * CD * CS + sbase;
#pragma unroll
    for (int i = 0; i < 8; i++) {
        int idx = tid + 256 * i, row = idx >> 4, ch = idx & 15;   // ch: float4 chunk (4 cols)
        float4 v = __ldg(reinterpret_cast<const float4*>(gx3f + (size_t)row * CS + ch * 4));
        float4 r = *reinterpret_cast<const float4*>(&srs[ch * 4]);
        __half2 h0 = __floats2half2_rn(v.x * r.x, v.y * r.y);
        __half2 h1 = __floats2half2_rn(v.z * r.z, v.w * r.w);
        uint2 u = { *(uint32_t*)&h0, *(uint32_t*)&h1 };
        *reinterpret_cast<uint2*>(gx3h + (size_t)row * CS + ch * 4) = u;
    }

    // release: E + x3h visible, then bump per-bh counter
    __threadfence();
    __syncthreads();
    if (tid == 0) atomicAdd(&g_done[bh], 1);
}

// ================= pv item body (R11 structure + dependency spin) =================
// CTA tile: 128(d) x 64(kc), sweep 16 s-chunks of 128.
// SMEM: A 32KB @0 | E0 16KB @32K | E1 16KB @48K
__device__ __forceinline__ void pv_body(char* smem, int bh, int kcbase,
                                        float* __restrict__ out) {
    const int tid = threadIdx.x, lane = tid & 31, wid = tid >> 5;
    const int wm = wid & 3, wn = wid >> 2;

    // acquire: wait for all 32 score items of this bh
    if (tid == 0) {
        while (*(volatile int*)&g_done[bh] < 32) __nanosleep(100);
    }
    __syncthreads();
    __threadfence();

    const uint32_t sbA  = smem_u32(smem);
    const uint32_t sbE0 = sbA + 32768;
    const uint32_t sbE1 = sbA + 49152;

    const __half* gA3 = g_x3h + (size_t)bh * CD * CS;
    const __half* gEb = g_E + ((size_t)bh * CS) * CS + kcbase;

    // prologue: E(0), A(0)
#pragma unroll
    for (int i = 0; i < 4; i++) {
        int idx = tid + 256 * i, row = idx >> 3, ch = idx & 7;
        cpa16(sbE0 + offE(row, ch), gEb + (size_t)row * CS + ch * 8);
    }
    CP_COMMIT();
#pragma unroll
    for (int i = 0; i < 8; i++) {
        int idx = tid + 256 * i, row = idx >> 4, ch = idx & 15;
        cpa16(sbA + off(row, ch), gA3 + (size_t)row * CS + ch * 8);
    }
    CP_COMMIT();

    float c[2][4][4];
#pragma unroll
    for (int mt = 0; mt < 2; mt++)
#pragma unroll
        for (int nt = 0; nt < 4; nt++)
#pragma unroll
            for (int q = 0; q < 4; q++) c[mt][nt][q] = 0.f;

    const int arow = wm * 32 + (lane & 15);
    const int ahb = lane >> 4;
    const int btrow = lane & 15;
    const int btch_base = wn * 4 + (lane >> 4);

    for (int st = 0; st < C_NT; st++) {
        const uint32_t sbE = (st & 1) ? sbE1 : sbE0;

        CP_WAIT0();
        __syncthreads();

        if (st + 1 < C_NT) {
            const __half* gE = gEb + (size_t)(st + 1) * 128 * CS;
            uint32_t dst = ((st + 1) & 1) ? sbE1 : sbE0;
#pragma unroll
            for (int i = 0; i < 4; i++) {
                int idx = tid + 256 * i, row = idx >> 3, ch = idx & 7;
                cpa16(dst + offE(row, ch), gE + (size_t)row * CS + ch * 8);
            }
            CP_COMMIT();
        }

#pragma unroll
        for (int ks = 0; ks < 8; ks++) {
            uint32_t a[2][4], b[2][4];
#pragma unroll
            for (int mt = 0; mt < 2; mt++)
                lds_x4(a[mt], sbA + off(arow + mt * 16, ks * 2 + ahb));
#pragma unroll
            for (int ntb = 0; ntb < 2; ntb++)
                lds_x4_t(b[ntb], sbE + offE(ks * 16 + btrow, btch_base + ntb * 2));
#pragma unroll
            for (int mt = 0; mt < 2; mt++)
#pragma unroll
                for (int ntb = 0; ntb < 2; ntb++) {
                    mma16816(c[mt][ntb * 2 + 0], a[mt], b[ntb][0], b[ntb][1]);
                    mma16816(c[mt][ntb * 2 + 1], a[mt], b[ntb][2], b[ntb][3]);
                }
        }
        __syncthreads();
        if (st + 1 < C_NT) {
#pragma unroll
            for (int i = 0; i < 8; i++) {
                int idx = tid + 256 * i, row = idx >> 4, ch = idx & 15;
                cpa16(sbA + off(row, ch), gA3 + (size_t)row * CS + (st + 1) * 128 + ch * 8);
            }
            CP_COMMIT();
        }
    }

    // epilogue: fp32 store out[bh][d][kc]
#pragma unroll
    for (int mt = 0; mt < 2; mt++) {
        const int d0 = wm * 32 + mt * 16 + (lane >> 2);
#pragma unroll
        for (int nt = 0; nt < 4; nt++) {
            const int col = kcbase + wn * 32 + nt * 8 + (lane & 3) * 2;
            float2 v0 = make_float2(c[mt][nt][0], c[mt][nt][1]);
            float2 v1 = make_float2(c[mt][nt][2], c[mt][nt][3]);
            *reinterpret_cast<float2*>(out + ((size_t)(bh * CD + d0)) * CS + col) = v0;
            *reinterpret_cast<float2*>(out + ((size_t)(bh * CD + d0 + 8)) * CS + col) = v1;
        }
    }
}

// ================= fused persistent kernel =================
__global__ void __launch_bounds__(256, 3) fused_kernel(const float* __restrict__ x1,
                                                       const float* __restrict__ x3,
                                                       float* __restrict__ out) {
    extern __shared__ char smem[];
    __shared__ int s_item;
    const int tid = threadIdx.x;

    for (;;) {
        if (tid == 0) s_item = atomicAdd(&g_next, 1);
        __syncthreads();
        const int item = s_item;
        if (item >= N_ITEMS) return;

        if (item < N_SCORE) {
            // bh-major: per-bh items finish early and consecutively
            score_body(smem, item >> 5, (item & 31) * 64, x1, x3);
        } else {
            const int j = item - N_SCORE;
            pv_body(smem, j >> 5, (j & 31) * 64, out);
        }
        __syncthreads();   // protect s_item + SMEM reuse across items
    }
}

// ================= launch =================
extern "C" void kernel_launch(void* const* d_in, const int* in_sizes, int n_in,
                              void* d_out, int out_size) {
    (void)in_sizes; (void)n_in; (void)out_size;
    const float* x1   = (const float*)d_in[0];
    const float* x2   = (const float*)d_in[1];
    const float* x3   = (const float*)d_in[2];
    const float* mask = (const float*)d_in[3];
    float* out = (float*)d_out;

    cudaFuncSetAttribute(fused_kernel, cudaFuncAttributeMaxDynamicSharedMemorySize, 65792);

    constexpr size_t TOT4 = ((size_t)C_BH * CS * CD / 4) + (size_t)CS * CS / 4;
    convert_kernel<<<(int)((TOT4 + 255) / 256), 256>>>(x2, mask);
    fused_kernel<<<GRID_P, 256, 65792>>>(x1, x3, out);
}

// round 15
// speedup vs baseline: 1.1222x; 1.1195x over previous
#include <cuda_runtime.h>
#include <cuda_fp16.h>
#include <cstdint>

#define CB 2
#define CH 16
#define CS 2048
#define CD 128

constexpr int C_BH = CB * CH;   // 32
constexpr int C_NT = CS / 128;  // 16 B/E tiles along S (128-wide)
constexpr int C_ST = CS / 64;   // 32 score s-tiles (64 rows each)

// -------- device scratch (allocation-free per harness rules) --------
__device__ __half    g_x2h[(size_t)C_BH * CS * CD];
__device__ __half    g_x3h[(size_t)C_BH * CD * CS];  // x3 * recip[s], fp16 (written by score)
__device__ uint16_t  g_masku[(size_t)CS * CS];       // (mask*log2e+16)*2048, u16 fixed point
__device__ __half    g_E[(size_t)C_BH * CS * CS];    // unnormalized exp * 2^-10, fp16

#define LOG2E_F 1.4426950408889634f
#define MQ_ENC  2954.6394367894f
#define MQ_DEC  4.8828125e-4f
#define MQ_BIAS (-26.0f)
__device__ __forceinline__ float c_scale_log2e() { return 0.08838834764831843f * 1.4426950408889634f; }

// -------- helpers --------
__device__ __forceinline__ uint32_t smem_u32(const void* p) {
    return (uint32_t)__cvta_generic_to_shared(p);
}
__device__ __forceinline__ float ex2f(float x) { float y; asm("ex2.approx.ftz.f32 %0, %1;" : "=f"(y) : "f"(x)); return y; }

// swizzled offset in a [rows x 128 halves/u16] tile: 256B rows, 16B chunks (ch 0..15)
__device__ __forceinline__ uint32_t off(int row, int ch) {
    return (uint32_t)(row * 256 + ((ch ^ (row & 7)) << 4));
}
// byte offset of 2B element [row][col] in the 256B-row layout
__device__ __forceinline__ uint32_t moff(int row, int col) {
    return (uint32_t)(row * 256 + ((((col >> 3) ^ (row & 7)) << 4) | ((col & 7) << 1)));
}
// swizzled offset in a [rows x 64 halves] tile: 128B rows, 16B chunks (ch 0..7)
__device__ __forceinline__ uint32_t offE(int row, int ch) {
    return (uint32_t)(row * 128 + ((ch ^ (row & 7)) << 4));
}

__device__ __forceinline__ void lds_x4(uint32_t a[4], uint32_t addr) {
    asm volatile("ldmatrix.sync.aligned.m8n8.x4.shared.b16 {%0,%1,%2,%3}, [%4];"
                 : "=r"(a[0]), "=r"(a[1]), "=r"(a[2]), "=r"(a[3]) : "r"(addr));
}
__device__ __forceinline__ void lds_x4_t(uint32_t a[4], uint32_t addr) {
    asm volatile("ldmatrix.sync.aligned.m8n8.x4.trans.shared.b16 {%0,%1,%2,%3}, [%4];"
                 : "=r"(a[0]), "=r"(a[1]), "=r"(a[2]), "=r"(a[3]) : "r"(addr));
}
__device__ __forceinline__ void mma16816(float c[4], const uint32_t a[4], uint32_t b0, uint32_t b1) {
    asm volatile("mma.sync.aligned.m16n8k16.row.col.f32.f16.f16.f32 "
                 "{%0,%1,%2,%3}, {%4,%5,%6,%7}, {%8,%9}, {%0,%1,%2,%3};"
                 : "+f"(c[0]), "+f"(c[1]), "+f"(c[2]), "+f"(c[3])
                 : "r"(a[0]), "r"(a[1]), "r"(a[2]), "r"(a[3]), "r"(b0), "r"(b1));
}
__device__ __forceinline__ void cpa16(uint32_t saddr, const void* g) {
    asm volatile("cp.async.cg.shared.global [%0], [%1], 16;" :: "r"(saddr), "l"(g));
}
#define CP_COMMIT() asm volatile("cp.async.commit_group;" ::: "memory")
#define CP_WAIT0()  asm volatile("cp.async.wait_group 0;" ::: "memory")

// ================= kernel 1: fp16 convert (x2) + mask -> u16 fixed point =================
__global__ void __launch_bounds__(256) convert_kernel(const float* __restrict__ x2,
                                                      const float* __restrict__ mask) {
    constexpr size_t SEG = (size_t)C_BH * CS * CD / 4;   // 2097152
    constexpr size_t SEGM = (size_t)CS * CS / 4;         // 1048576
    size_t t = (size_t)blockIdx.x * blockDim.x + threadIdx.x;
    if (t < SEG) {
        float4 v = reinterpret_cast<const float4*>(x2)[t];
        __half2 h0 = __floats2half2_rn(v.x, v.y), h1 = __floats2half2_rn(v.z, v.w);
        uint2 u = { *(uint32_t*)&h0, *(uint32_t*)&h1 };
        reinterpret_cast<uint2*>(g_x2h)[t] = u;
    } else if (t < SEG + SEGM) {
        t -= SEG;
        float4 v = reinterpret_cast<const float4*>(mask)[t];
        float q0 = fminf(fmaxf(fmaf(v.x, MQ_ENC, 32768.f), 0.f), 65535.f);
        float q1 = fminf(fmaxf(fmaf(v.y, MQ_ENC, 32768.f), 0.f), 65535.f);
        float q2 = fminf(fmaxf(fmaf(v.z, MQ_ENC, 32768.f), 0.f), 65535.f);
        float q3 = fminf(fmaxf(fmaf(v.w, MQ_ENC, 32768.f), 0.f), 65535.f);
        uint32_t w0 = __float2uint_rn(q0) | (__float2uint_rn(q1) << 16);
        uint32_t w1 = __float2uint_rn(q2) | (__float2uint_rn(q3) << 16);
        uint2 u = { w0, w1 };
        reinterpret_cast<uint2*>(g_masku)[t] = u;
    }
}

// ================= kernel 2: scores -> exp -> E + rowsum + x3 scaling =================
// CTA tile: 64(s) x 128(kc per iter, sweep 16). bh = bid&31 (s-major), sbase = (bid>>5)*64.
// Warp layout: 2m x 4n, warp tile 32x32. 32 accums/thread.
// Loop: 2 syncs + 1 wait. Mask refilled per-warp into its OWN 32x32 block of the
// shared swizzled M buffer (write region == own read region -> no barrier).
// SMEM: A 16KB @0 | B 32KB @16K | M(u16) 16KB @48K | rowsum 256B @64K  (65.8KB, 3 CTA/SM)
__global__ void __launch_bounds__(256, 3) score_kernel(const float* __restrict__ x1,
                                                       const float* __restrict__ x3) {
    extern __shared__ char smem[];
    const int tid = threadIdx.x, lane = tid & 31, wid = tid >> 5;
    const int wm = wid & 1, wn = wid >> 1;
    const int bh = blockIdx.x & 31;
    const int sbase = (blockIdx.x >> 5) * 64;

    const uint32_t sbA = smem_u32(smem);
    const uint32_t sbB = sbA + 16384;
    const uint32_t sbM = sbA + 49152;
    char* smM = smem + 49152;
    float* srs = reinterpret_cast<float*>(smem + 65536);

    if (tid < 64) srs[tid] = 0.f;

    // per-warp M block mapping: rows wm*32+(idx>>2), chunks wn*4+(idx&3)
    const int mrow_base = wm * 32;
    const int mch_base  = wn * 4;
    const uint16_t* gM = g_masku + (size_t)sbase * CS;

    // prologue: B(0) group, then M(0) group (per-warp blocks, one commit per thread)
    const __half* gB0 = g_x2h + (size_t)bh * CS * CD;
#pragma unroll
    for (int i = 0; i < 8; i++) {
        int idx = tid + 256 * i, row = idx >> 4, ch = idx & 15;
        cpa16(sbB + off(row, ch), gB0 + row * CD + ch * 8);
    }
    CP_COMMIT();
#pragma unroll
    for (int i = 0; i < 4; i++) {
        int idx = lane + 32 * i;
        int row = mrow_base + (idx >> 2), ch = mch_base + (idx & 3);
        cpa16(sbM + off(row, ch), gM + (size_t)row * CS + ch * 8);
    }
    CP_COMMIT();

    // stage A: x1 fp32 -> fp16 inline (64 rows x 128 cols)
    const float* gA = x1 + ((size_t)(bh * CS + sbase)) * CD;
#pragma unroll
    for (int i = 0; i < 4; i++) {
        int idx = tid + 256 * i, row = idx >> 4, ch = idx & 15;
        const float4* s = reinterpret_cast<const float4*>(gA + row * CD + ch * 8);
        float4 v0 = s[0], v1 = s[1];
        __half2 h0 = __floats2half2_rn(v0.x, v0.y), h1 = __floats2half2_rn(v0.z, v0.w);
        __half2 h2 = __floats2half2_rn(v1.x, v1.y), h3 = __floats2half2_rn(v1.z, v1.w);
        uint4 u = { *(uint32_t*)&h0, *(uint32_t*)&h1, *(uint32_t*)&h2, *(uint32_t*)&h3 };
        *reinterpret_cast<uint4*>(smem + off(row, ch)) = u;
    }

    const float c1 = c_scale_log2e();
    float rs0 = 0.f, rs1 = 0.f, rs2 = 0.f, rs3 = 0.f;

    const int arow = wm * 32 + (lane & 15);
    const int brow = wn * 32 + (lane & 7) + ((lane & 16) >> 1);
    const int ahb = lane >> 4;
    const int bhb = (lane >> 3) & 1;

    for (int kct = 0; kct < C_NT; kct++) {
        CP_WAIT0();          // B(kct) AND M(kct) ready
        __syncthreads();

        float c[2][4][4];
#pragma unroll
        for (int mt = 0; mt < 2; mt++)
#pragma unroll
            for (int nt = 0; nt < 4; nt++)
#pragma unroll
                for (int q = 0; q < 4; q++) c[mt][nt][q] = 0.f;

#pragma unroll
        for (int ks = 0; ks < 8; ks++) {
            uint32_t a[2][4], b[2][4];
#pragma unroll
            for (int mt = 0; mt < 2; mt++)
                lds_x4(a[mt], sbA + off(arow + mt * 16, ks * 2 + ahb));
#pragma unroll
            for (int ntb = 0; ntb < 2; ntb++)
                lds_x4(b[ntb], sbB + off(brow + ntb * 16, ks * 2 + bhb));
#pragma unroll
            for (int mt = 0; mt < 2; mt++)
#pragma unroll
                for (int ntb = 0; ntb < 2; ntb++) {
                    mma16816(c[mt][ntb * 2 + 0], a[mt], b[ntb][0], b[ntb][1]);
                    mma16816(c[mt][ntb * 2 + 1], a[mt], b[ntb][2], b[ntb][3]);
                }
        }
        __syncthreads();     // B consumed by all warps -> safe to refill

        // refill B(kct+1): hidden under the epilogue below
        if (kct + 1 < C_NT) {
            const __half* gB = g_x2h + ((size_t)(bh * CS + (kct + 1) * 128)) * CD;
#pragma unroll
            for (int i = 0; i < 8; i++) {
                int idx = tid + 256 * i, row = idx >> 4, ch = idx & 15;
                cpa16(sbB + off(row, ch), gB + row * CD + ch * 8);
            }
            CP_COMMIT();
        }

        // epilogue: u16 mask from SMEM (ready since loop top) -> exp -> E store + rowsum
        const int gcb = kct * 128;
#pragma unroll
        for (int mt = 0; mt < 2; mt++) {
            const int r0 = wm * 32 + mt * 16 + (lane >> 2);
            __half* ep0 = g_E + ((size_t)(bh * CS + sbase + r0)) * CS + gcb;
            __half* ep1 = ep0 + 8 * CS;
#pragma unroll
            for (int nt = 0; nt < 4; nt++) {
                const int col = wn * 32 + nt * 8 + (lane & 3) * 2;
                uint32_t mw0 = *reinterpret_cast<const uint32_t*>(smM + moff(r0, col));
                uint32_t mw1 = *reinterpret_cast<const uint32_t*>(smM + moff(r0 + 8, col));
                float m00 = fmaf((float)(mw0 & 0xffff), MQ_DEC, MQ_BIAS);
                float m01 = fmaf((float)(mw0 >> 16),    MQ_DEC, MQ_BIAS);
                float m10 = fmaf((float)(mw1 & 0xffff), MQ_DEC, MQ_BIAS);
                float m11 = fmaf((float)(mw1 >> 16),    MQ_DEC, MQ_BIAS);
                float e00 = ex2f(fmaf(c[mt][nt][0], c1, m00));
                float e01 = ex2f(fmaf(c[mt][nt][1], c1, m01));
                float e10 = ex2f(fmaf(c[mt][nt][2], c1, m10));
                float e11 = ex2f(fmaf(c[mt][nt][3], c1, m11));
                *reinterpret_cast<__half2*>(ep0 + col) = __floats2half2_rn(e00, e01);
                *reinterpret_cast<__half2*>(ep1 + col) = __floats2half2_rn(e10, e11);
                if (mt == 0) { rs0 += e00 + e01; rs1 += e10 + e11; }
                else         { rs2 += e00 + e01; rs3 += e10 + e11; }
            }
        }

        // refill OWN M(kct+1) block: write region == this warp's read region -> no barrier
        if (kct + 1 < C_NT) {
#pragma unroll
            for (int i = 0; i < 4; i++) {
                int idx = lane + 32 * i;
                int row = mrow_base + (idx >> 2), ch = mch_base + (idx & 3);
                cpa16(sbM + off(row, ch), gM + (size_t)row * CS + (kct + 1) * 128 + ch * 8);
            }
            CP_COMMIT();
        }
    }

    rs0 += __shfl_xor_sync(~0u, rs0, 1); rs0 += __shfl_xor_sync(~0u, rs0, 2);
    rs1 += __shfl_xor_sync(~0u, rs1, 1); rs1 += __shfl_xor_sync(~0u, rs1, 2);
    rs2 += __shfl_xor_sync(~0u, rs2, 1); rs2 += __shfl_xor_sync(~0u, rs2, 2);
    rs3 += __shfl_xor_sync(~0u, rs3, 1); rs3 += __shfl_xor_sync(~0u, rs3, 2);
    if ((lane & 3) == 0) {
        int r = wm * 32 + (lane >> 2);
        atomicAdd(&srs[r],      rs0);
        atomicAdd(&srs[r + 8],  rs1);
        atomicAdd(&srs[r + 16], rs2);
        atomicAdd(&srs[r + 24], rs3);
    }
    __syncthreads();
    if (tid < 64) srs[tid] = 1.0f / srs[tid];
    __syncthreads();

    // tail: x3h[bh][d][sbase+j] = fp16(x3 * recip[j]), 128 rows x 64 cols
    const float* gx3f = x3 + (size_t)bh * CD * CS + sbase;
    __half* gx3h = g_x3h + (size_t)bh * CD * CS + sbase;
#pragma unroll
    for (int i = 0; i < 8; i++) {
        int idx = tid + 256 * i, row = idx >> 4, ch = idx & 15;   // ch: float4 chunk (4 cols)
        float4 v = __ldg(reinterpret_cast<const float4*>(gx3f + (size_t)row * CS + ch * 4));
        float4 r = *reinterpret_cast<const float4*>(&srs[ch * 4]);
        __half2 h0 = __floats2half2_rn(v.x * r.x, v.y * r.y);
        __half2 h1 = __floats2half2_rn(v.z * r.z, v.w * r.w);
        uint2 u = { *(uint32_t*)&h0, *(uint32_t*)&h1 };
        *reinterpret_cast<uint2*>(gx3h + (size_t)row * CS + ch * 4) = u;
    }
}

// ================= kernel 3: out = x3' @ E  (output-stationary) =================
// CTA tile: 128(d) x 64(kc). bh reversed (L2-hot E first). kcbase = (bid&31)*64.
// Warp layout: 4m x 2n, warp tile 32x32. 32 accums/thread.
// SMEM: A 32KB @0 | E0 16KB @32K | E1 16KB @48K  (64KB, 3 CTA/SM)
__global__ void __launch_bounds__(256, 3) pv_kernel(float* __restrict__ out) {
    extern __shared__ char smem[];
    const int tid = threadIdx.x, lane = tid & 31, wid = tid >> 5;
    const int wm = wid & 3, wn = wid >> 2;
    const int bh = (C_BH - 1) - (blockIdx.x >> 5);
    const int kcbase = (blockIdx.x & 31) * 64;

    const uint32_t sbA  = smem_u32(smem);
    const uint32_t sbE0 = sbA + 32768;
    const uint32_t sbE1 = sbA + 49152;

    const __half* gA3 = g_x3h + (size_t)bh * CD * CS;
    const __half* gEb = g_E + ((size_t)bh * CS) * CS + kcbase;

    // prologue: E(0), A(0)
#pragma unroll
    for (int i = 0; i < 4; i++) {
        int idx = tid + 256 * i, row = idx >> 3, ch = idx & 7;
        cpa16(sbE0 + offE(row, ch), gEb + (size_t)row * CS + ch * 8);
    }
    CP_COMMIT();
#pragma unroll
    for (int i = 0; i < 8; i++) {
        int idx = tid + 256 * i, row = idx >> 4, ch = idx & 15;
        cpa16(sbA + off(row, ch), gA3 + (size_t)row * CS + ch * 8);
    }
    CP_COMMIT();

    float c[2][4][4];
#pragma unroll
    for (int mt = 0; mt < 2; mt++)
#pragma unroll
        for (int nt = 0; nt < 4; nt++)
#pragma unroll
            for (int q = 0; q < 4; q++) c[mt][nt][q] = 0.f;

    const int arow = wm * 32 + (lane & 15);
    const int ahb = lane >> 4;
    const int btrow = lane & 15;
    const int btch_base = wn * 4 + (lane >> 4);

    for (int st = 0; st < C_NT; st++) {
        const uint32_t sbE = (st & 1) ? sbE1 : sbE0;

        CP_WAIT0();
        __syncthreads();

        // prefetch E(st+1) into other buffer; hides under MMA below
        if (st + 1 < C_NT) {
            const __half* gE = gEb + (size_t)(st + 1) * 128 * CS;
            uint32_t dst = ((st + 1) & 1) ? sbE1 : sbE0;
#pragma unroll
            for (int i = 0; i < 4; i++) {
                int idx = tid + 256 * i, row = idx >> 3, ch = idx & 7;
                cpa16(dst + offE(row, ch), gE + (size_t)row * CS + ch * 8);
            }
            CP_COMMIT();
        }

#pragma unroll
        for (int ks = 0; ks < 8; ks++) {
            uint32_t a[2][4], b[2][4];
#pragma unroll
            for (int mt = 0; mt < 2; mt++)
                lds_x4(a[mt], sbA + off(arow + mt * 16, ks * 2 + ahb));
#pragma unroll
            for (int ntb = 0; ntb < 2; ntb++)
                lds_x4_t(b[ntb], sbE + offE(ks * 16 + btrow, btch_base + ntb * 2));
#pragma unroll
            for (int mt = 0; mt < 2; mt++)
#pragma unroll
                for (int ntb = 0; ntb < 2; ntb++) {
                    mma16816(c[mt][ntb * 2 + 0], a[mt], b[ntb][0], b[ntb][1]);
                    mma16816(c[mt][ntb * 2 + 1], a[mt], b[ntb][2], b[ntb][3]);
                }
        }
        __syncthreads();
        // refill A(st+1) (L2-resident x3h; lands before next wait)
        if (st + 1 < C_NT) {
#pragma unroll
            for (int i = 0; i < 8; i++) {
                int idx = tid + 256 * i, row = idx >> 4, ch = idx & 15;
                cpa16(sbA + off(row, ch), gA3 + (size_t)row * CS + (st + 1) * 128 + ch * 8);
            }
            CP_COMMIT();
        }
    }

    // epilogue: fp32 store out[bh][d][kc]
#pragma unroll
    for (int mt = 0; mt < 2; mt++) {
        const int d0 = wm * 32 + mt * 16 + (lane >> 2);
#pragma unroll
        for (int nt = 0; nt < 4; nt++) {
            const int col = kcbase + wn * 32 + nt * 8 + (lane & 3) * 2;
            float2 v0 = make_float2(c[mt][nt][0], c[mt][nt][1]);
            float2 v1 = make_float2(c[mt][nt][2], c[mt][nt][3]);
            *reinterpret_cast<float2*>(out + ((size_t)(bh * CD + d0)) * CS + col) = v0;
            *reinterpret_cast<float2*>(out + ((size_t)(bh * CD + d0 + 8)) * CS + col) = v1;
        }
    }
}

// ================= launch =================
extern "C" void kernel_launch(void* const* d_in, const int* in_sizes, int n_in,
                              void* d_out, int out_size) {
    (void)in_sizes; (void)n_in; (void)out_size;
    const float* x1   = (const float*)d_in[0];
    const float* x2   = (const float*)d_in[1];
    const float* x3   = (const float*)d_in[2];
    const float* mask = (const float*)d_in[3];
    float* out = (float*)d_out;

    cudaFuncSetAttribute(score_kernel, cudaFuncAttributeMaxDynamicSharedMemorySize, 65792);
    cudaFuncSetAttribute(pv_kernel,    cudaFuncAttributeMaxDynamicSharedMemorySize, 65536);

    constexpr size_t TOT4 = ((size_t)C_BH * CS * CD / 4) + (size_t)CS * CS / 4;
    convert_kernel<<<(int)((TOT4 + 255) / 256), 256>>>(x2, mask);
    score_kernel<<<C_BH * C_ST, 256, 65792>>>(x1, x3);
    pv_kernel<<<C_BH * C_ST, 256, 65536>>>(out);
}

// round 16
// speedup vs baseline: 1.1711x; 1.0436x over previous
#include <cuda_runtime.h>
#include <cuda_fp16.h>
#include <cstdint>

#define CB 2
#define CH 16
#define CS 2048
#define CD 128

constexpr int C_BH = CB * CH;   // 32
constexpr int C_NT = CS / 128;  // 16 B/E tiles along S (128-wide)
constexpr int C_ST = CS / 64;   // 32 score s-tiles (64 rows each)

// -------- device scratch (allocation-free per harness rules) --------
__device__ __half    g_x2h[(size_t)C_BH * CS * CD];
__device__ __half    g_x3h[(size_t)C_BH * CD * CS];  // x3 * recip[s], fp16 (written by score)
__device__ uint16_t  g_masku[(size_t)CS * CS];       // (mask*log2e+16)*2048, u16 fixed point
__device__ __half    g_E[(size_t)C_BH * CS * CS];    // unnormalized exp * 2^-10, fp16

#define LOG2E_F 1.4426950408889634f
#define MQ_ENC  2954.6394367894f
#define MQ_DEC  4.8828125e-4f
#define MQ_BIAS (-26.0f)
__device__ __forceinline__ float c_scale_log2e() { return 0.08838834764831843f * 1.4426950408889634f; }

// -------- helpers --------
__device__ __forceinline__ uint32_t smem_u32(const void* p) {
    return (uint32_t)__cvta_generic_to_shared(p);
}
__device__ __forceinline__ float ex2f(float x) { float y; asm("ex2.approx.ftz.f32 %0, %1;" : "=f"(y) : "f"(x)); return y; }

// swizzled offset in a [rows x 128 halves/u16] tile: 256B rows, 16B chunks (ch 0..15)
__device__ __forceinline__ uint32_t off(int row, int ch) {
    return (uint32_t)(row * 256 + ((ch ^ (row & 7)) << 4));
}
// byte offset of 2B element [row][col] in the 256B-row layout
__device__ __forceinline__ uint32_t moff(int row, int col) {
    return (uint32_t)(row * 256 + ((((col >> 3) ^ (row & 7)) << 4) | ((col & 7) << 1)));
}
// swizzled offset in a [rows x 64 halves] tile: 128B rows, 16B chunks (ch 0..7)
__device__ __forceinline__ uint32_t offE(int row, int ch) {
    return (uint32_t)(row * 128 + ((ch ^ (row & 7)) << 4));
}

__device__ __forceinline__ void lds_x4(uint32_t a[4], uint32_t addr) {
    asm volatile("ldmatrix.sync.aligned.m8n8.x4.shared.b16 {%0,%1,%2,%3}, [%4];"
                 : "=r"(a[0]), "=r"(a[1]), "=r"(a[2]), "=r"(a[3]) : "r"(addr));
}
__device__ __forceinline__ void lds_x4_t(uint32_t a[4], uint32_t addr) {
    asm volatile("ldmatrix.sync.aligned.m8n8.x4.trans.shared.b16 {%0,%1,%2,%3}, [%4];"
                 : "=r"(a[0]), "=r"(a[1]), "=r"(a[2]), "=r"(a[3]) : "r"(addr));
}
__device__ __forceinline__ void mma16816(float c[4], const uint32_t a[4], uint32_t b0, uint32_t b1) {
    asm volatile("mma.sync.aligned.m16n8k16.row.col.f32.f16.f16.f32 "
                 "{%0,%1,%2,%3}, {%4,%5,%6,%7}, {%8,%9}, {%0,%1,%2,%3};"
                 : "+f"(c[0]), "+f"(c[1]), "+f"(c[2]), "+f"(c[3])
                 : "r"(a[0]), "r"(a[1]), "r"(a[2]), "r"(a[3]), "r"(b0), "r"(b1));
}
__device__ __forceinline__ void cpa16(uint32_t saddr, const void* g) {
    asm volatile("cp.async.cg.shared.global [%0], [%1], 16;" :: "r"(saddr), "l"(g));
}
#define CP_COMMIT() asm volatile("cp.async.commit_group;" ::: "memory")
#define CP_WAIT0()  asm volatile("cp.async.wait_group 0;" ::: "memory")
#define CP_WAIT1()  asm volatile("cp.async.wait_group 1;" ::: "memory")

// ================= kernel 1: fp16 convert (x2) + mask -> u16, MLP=4 =================
constexpr size_t CV_SEG  = (size_t)C_BH * CS * CD / 4;   // 2097152 float4s of x2
constexpr size_t CV_SEGM = (size_t)CS * CS / 4;          // 1048576 float4s of mask
constexpr size_t CV_TOT  = CV_SEG + CV_SEGM;             // 3145728
constexpr size_t CV_Q    = CV_TOT / 4;                   // 786432 threads

__device__ __forceinline__ void cv_store(size_t t, float4 v) {
    if (t < CV_SEG) {
        __half2 h0 = __floats2half2_rn(v.x, v.y), h1 = __floats2half2_rn(v.z, v.w);
        uint2 u = { *(uint32_t*)&h0, *(uint32_t*)&h1 };
        reinterpret_cast<uint2*>(g_x2h)[t] = u;
    } else {
        float q0 = fminf(fmaxf(fmaf(v.x, MQ_ENC, 32768.f), 0.f), 65535.f);
        float q1 = fminf(fmaxf(fmaf(v.y, MQ_ENC, 32768.f), 0.f), 65535.f);
        float q2 = fminf(fmaxf(fmaf(v.z, MQ_ENC, 32768.f), 0.f), 65535.f);
        float q3 = fminf(fmaxf(fmaf(v.w, MQ_ENC, 32768.f), 0.f), 65535.f);
        uint32_t w0 = __float2uint_rn(q0) | (__float2uint_rn(q1) << 16);
        uint32_t w1 = __float2uint_rn(q2) | (__float2uint_rn(q3) << 16);
        uint2 u = { w0, w1 };
        reinterpret_cast<uint2*>(g_masku)[t - CV_SEG] = u;
    }
}

__global__ void __launch_bounds__(256) convert_kernel(const float* __restrict__ x2,
                                                      const float* __restrict__ mask) {
    const size_t i = (size_t)blockIdx.x * blockDim.x + threadIdx.x;
    if (i >= CV_Q) return;
    const size_t t0 = i, t1 = i + CV_Q, t2 = i + 2 * CV_Q, t3 = i + 3 * CV_Q;
    // issue all 4 loads before any store (MLP=4)
    const float4* p0 = (t0 < CV_SEG ? reinterpret_cast<const float4*>(x2) + t0
                                    : reinterpret_cast<const float4*>(mask) + (t0 - CV_SEG));
    const float4* p1 = (t1 < CV_SEG ? reinterpret_cast<const float4*>(x2) + t1
                                    : reinterpret_cast<const float4*>(mask) + (t1 - CV_SEG));
    const float4* p2 = (t2 < CV_SEG ? reinterpret_cast<const float4*>(x2) + t2
                                    : reinterpret_cast<const float4*>(mask) + (t2 - CV_SEG));
    const float4* p3 = (t3 < CV_SEG ? reinterpret_cast<const float4*>(x2) + t3
                                    : reinterpret_cast<const float4*>(mask) + (t3 - CV_SEG));
    float4 v0 = __ldg(p0), v1 = __ldg(p1), v2 = __ldg(p2), v3 = __ldg(p3);
    cv_store(t0, v0);
    cv_store(t1, v1);
    cv_store(t2, v2);
    cv_store(t3, v3);
}

// ================= kernel 2: scores -> exp -> E + rowsum + x3 scaling (R11) =================
// CTA tile: 64(s) x 128(kc per iter, sweep 16). bh = bid&31 (s-major), sbase = (bid>>5)*64.
// Warp layout: 2m x 4n, warp tile 32x32. 32 accums/thread.
// SMEM: A 16KB @0 | B 32KB @16K | M(u16) 16KB @48K | rowsum 256B @64K  (65.8KB, 3 CTA/SM)
__global__ void __launch_bounds__(256, 3) score_kernel(const float* __restrict__ x1,
                                                       const float* __restrict__ x3) {
    extern __shared__ char smem[];
    const int tid = threadIdx.x, lane = tid & 31, wid = tid >> 5;
    const int wm = wid & 1, wn = wid >> 1;
    const int bh = blockIdx.x & 31;
    const int sbase = (blockIdx.x >> 5) * 64;

    const uint32_t sbA = smem_u32(smem);
    const uint32_t sbB = sbA + 16384;
    const uint32_t sbM = sbA + 49152;
    char* smM = smem + 49152;
    float* srs = reinterpret_cast<float*>(smem + 65536);

    if (tid < 64) srs[tid] = 0.f;

    // prologue: B(0) group, then M(0) group
    const __half* gB0 = g_x2h + (size_t)bh * CS * CD;
#pragma unroll
    for (int i = 0; i < 8; i++) {
        int idx = tid + 256 * i, row = idx >> 4, ch = idx & 15;
        cpa16(sbB + off(row, ch), gB0 + row * CD + ch * 8);
    }
    CP_COMMIT();
    const uint16_t* gM = g_masku + (size_t)sbase * CS;
#pragma unroll
    for (int i = 0; i < 4; i++) {
        int idx = tid + 256 * i, row = idx >> 4, ch = idx & 15;
        cpa16(sbM + off(row, ch), gM + (size_t)row * CS + ch * 8);
    }
    CP_COMMIT();

    // stage A: x1 fp32 -> fp16 inline (64 rows x 128 cols)
    const float* gA = x1 + ((size_t)(bh * CS + sbase)) * CD;
#pragma unroll
    for (int i = 0; i < 4; i++) {
        int idx = tid + 256 * i, row = idx >> 4, ch = idx & 15;
        const float4* s = reinterpret_cast<const float4*>(gA + row * CD + ch * 8);
        float4 v0 = s[0], v1 = s[1];
        __half2 h0 = __floats2half2_rn(v0.x, v0.y), h1 = __floats2half2_rn(v0.z, v0.w);
        __half2 h2 = __floats2half2_rn(v1.x, v1.y), h3 = __floats2half2_rn(v1.z, v1.w);
        uint4 u = { *(uint32_t*)&h0, *(uint32_t*)&h1, *(uint32_t*)&h2, *(uint32_t*)&h3 };
        *reinterpret_cast<uint4*>(smem + off(row, ch)) = u;
    }

    const float c1 = c_scale_log2e();
    float rs0 = 0.f, rs1 = 0.f, rs2 = 0.f, rs3 = 0.f;

    const int arow = wm * 32 + (lane & 15);
    const int brow = wn * 32 + (lane & 7) + ((lane & 16) >> 1);
    const int ahb = lane >> 4;
    const int bhb = (lane >> 3) & 1;

    for (int kct = 0; kct < C_NT; kct++) {
        CP_WAIT1();          // B(kct) ready; M(kct) in flight under MMA
        __syncthreads();

        float c[2][4][4];
#pragma unroll
        for (int mt = 0; mt < 2; mt++)
#pragma unroll
            for (int nt = 0; nt < 4; nt++)
#pragma unroll
                for (int q = 0; q < 4; q++) c[mt][nt][q] = 0.f;

#pragma unroll
        for (int ks = 0; ks < 8; ks++) {
            uint32_t a[2][4], b[2][4];
#pragma unroll
            for (int mt = 0; mt < 2; mt++)
                lds_x4(a[mt], sbA + off(arow + mt * 16, ks * 2 + ahb));
#pragma unroll
            for (int ntb = 0; ntb < 2; ntb++)
                lds_x4(b[ntb], sbB + off(brow + ntb * 16, ks * 2 + bhb));
#pragma unroll
            for (int mt = 0; mt < 2; mt++)
#pragma unroll
                for (int ntb = 0; ntb < 2; ntb++) {
                    mma16816(c[mt][ntb * 2 + 0], a[mt], b[ntb][0], b[ntb][1]);
                    mma16816(c[mt][ntb * 2 + 1], a[mt], b[ntb][2], b[ntb][3]);
                }
        }
        __syncthreads();
        if (kct + 1 < C_NT) {
            const __half* gB = g_x2h + ((size_t)(bh * CS + (kct + 1) * 128)) * CD;
#pragma unroll
            for (int i = 0; i < 8; i++) {
                int idx = tid + 256 * i, row = idx >> 4, ch = idx & 15;
                cpa16(sbB + off(row, ch), gB + row * CD + ch * 8);
            }
            CP_COMMIT();
            CP_WAIT1();      // M(kct) ready; B(kct+1) stays in flight
        } else {
            CP_WAIT0();
        }
        __syncthreads();

        // epilogue: u16 mask from SMEM -> exp -> E store + rowsum
        const int gcb = kct * 128;
#pragma unroll
        for (int mt = 0; mt < 2; mt++) {
            const int r0 = wm * 32 + mt * 16 + (lane >> 2);
            __half* ep0 = g_E + ((size_t)(bh * CS + sbase + r0)) * CS + gcb;
            __half* ep1 = ep0 + 8 * CS;
#pragma unroll
            for (int nt = 0; nt < 4; nt++) {
                const int col = wn * 32 + nt * 8 + (lane & 3) * 2;
                uint32_t mw0 = *reinterpret_cast<const uint32_t*>(smM + moff(r0, col));
                uint32_t mw1 = *reinterpret_cast<const uint32_t*>(smM + moff(r0 + 8, col));
                float m00 = fmaf((float)(mw0 & 0xffff), MQ_DEC, MQ_BIAS);
                float m01 = fmaf((float)(mw0 >> 16),    MQ_DEC, MQ_BIAS);
                float m10 = fmaf((float)(mw1 & 0xffff), MQ_DEC, MQ_BIAS);
                float m11 = fmaf((float)(mw1 >> 16),    MQ_DEC, MQ_BIAS);
                float e00 = ex2f(fmaf(c[mt][nt][0], c1, m00));
                float e01 = ex2f(fmaf(c[mt][nt][1], c1, m01));
                float e10 = ex2f(fmaf(c[mt][nt][2], c1, m10));
                float e11 = ex2f(fmaf(c[mt][nt][3], c1, m11));
                *reinterpret_cast<__half2*>(ep0 + col) = __floats2half2_rn(e00, e01);
                *reinterpret_cast<__half2*>(ep1 + col) = __floats2half2_rn(e10, e11);
                if (mt == 0) { rs0 += e00 + e01; rs1 += e10 + e11; }
                else         { rs2 += e00 + e01; rs3 += e10 + e11; }
            }
        }
        __syncthreads();
        if (kct + 1 < C_NT) {
#pragma unroll
            for (int i = 0; i < 4; i++) {
                int idx = tid + 256 * i, row = idx >> 4, ch = idx & 15;
                cpa16(sbM + off(row, ch), gM + (size_t)row * CS + (kct + 1) * 128 + ch * 8);
            }
            CP_COMMIT();
        }
    }

    rs0 += __shfl_xor_sync(~0u, rs0, 1); rs0 += __shfl_xor_sync(~0u, rs0, 2);
    rs1 += __shfl_xor_sync(~0u, rs1, 1); rs1 += __shfl_xor_sync(~0u, rs1, 2);
    rs2 += __shfl_xor_sync(~0u, rs2, 1); rs2 += __shfl_xor_sync(~0u, rs2, 2);
    rs3 += __shfl_xor_sync(~0u, rs3, 1); rs3 += __shfl_xor_sync(~0u, rs3, 2);
    if ((lane & 3) == 0) {
        int r = wm * 32 + (lane >> 2);
        atomicAdd(&srs[r],      rs0);
        atomicAdd(&srs[r + 8],  rs1);
        atomicAdd(&srs[r + 16], rs2);
        atomicAdd(&srs[r + 24], rs3);
    }
    __syncthreads();
    if (tid < 64) srs[tid] = 1.0f / srs[tid];
    __syncthreads();

    // tail: x3h[bh][d][sbase+j] = fp16(x3 * recip[j]), 128 rows x 64 cols
    const float* gx3f = x3 + (size_t)bh * CD * CS + sbase;
    __half* gx3h = g_x3h + (size_t)bh * CD * CS + sbase;
#pragma unroll
    for (int i = 0; i < 8; i++) {
        int idx = tid + 256 * i, row = idx >> 4, ch = idx & 15;   // ch: float4 chunk (4 cols)
        float4 v = __ldg(reinterpret_cast<const float4*>(gx3f + (size_t)row * CS + ch * 4));
        float4 r = *reinterpret_cast<const float4*>(&srs[ch * 4]);
        __half2 h0 = __floats2half2_rn(v.x * r.x, v.y * r.y);
        __half2 h1 = __floats2half2_rn(v.z * r.z, v.w * r.w);
        uint2 u = { *(uint32_t*)&h0, *(uint32_t*)&h1 };
        *reinterpret_cast<uint2*>(gx3h + (size_t)row * CS + ch * 4) = u;
    }
}

// ================= kernel 3: out = x3' @ E  (output-stationary, R11) =================
// CTA tile: 128(d) x 64(kc). bh reversed (L2-hot E first). kcbase = (bid&31)*64.
// Warp layout: 4m x 2n, warp tile 32x32. 32 accums/thread.
// SMEM: A 32KB @0 | E0 16KB @32K | E1 16KB @48K  (64KB, 3 CTA/SM)
__global__ void __launch_bounds__(256, 3) pv_kernel(float* __restrict__ out) {
    extern __shared__ char smem[];
    const int tid = threadIdx.x, lane = tid & 31, wid = tid >> 5;
    const int wm = wid & 3, wn = wid >> 2;
    const int bh = (C_BH - 1) - (blockIdx.x >> 5);
    const int kcbase = (blockIdx.x & 31) * 64;

    const uint32_t sbA  = smem_u32(smem);
    const uint32_t sbE0 = sbA + 32768;
    const uint32_t sbE1 = sbA + 49152;

    const __half* gA3 = g_x3h + (size_t)bh * CD * CS;
    const __half* gEb = g_E + ((size_t)bh * CS) * CS + kcbase;

    // prologue: E(0), A(0)
#pragma unroll
    for (int i = 0; i < 4; i++) {
        int idx = tid + 256 * i, row = idx >> 3, ch = idx & 7;
        cpa16(sbE0 + offE(row, ch), gEb + (size_t)row * CS + ch * 8);
    }
    CP_COMMIT();
#pragma unroll
    for (int i = 0; i < 8; i++) {
        int idx = tid + 256 * i, row = idx >> 4, ch = idx & 15;
        cpa16(sbA + off(row, ch), gA3 + (size_t)row * CS + ch * 8);
    }
    CP_COMMIT();

    float c[2][4][4];
#pragma unroll
    for (int mt = 0; mt < 2; mt++)
#pragma unroll
        for (int nt = 0; nt < 4; nt++)
#pragma unroll
            for (int q = 0; q < 4; q++) c[mt][nt][q] = 0.f;

    const int arow = wm * 32 + (lane & 15);
    const int ahb = lane >> 4;
    const int btrow = lane & 15;
    const int btch_base = wn * 4 + (lane >> 4);

    for (int st = 0; st < C_NT; st++) {
        const uint32_t sbE = (st & 1) ? sbE1 : sbE0;

        CP_WAIT0();
        __syncthreads();

        // prefetch E(st+1) into other buffer; hides under MMA below
        if (st + 1 < C_NT) {
            const __half* gE = gEb + (size_t)(st + 1) * 128 * CS;
            uint32_t dst = ((st + 1) & 1) ? sbE1 : sbE0;
#pragma unroll
            for (int i = 0; i < 4; i++) {
                int idx = tid + 256 * i, row = idx >> 3, ch = idx & 7;
                cpa16(dst + offE(row, ch), gE + (size_t)row * CS + ch * 8);
            }
            CP_COMMIT();
        }

#pragma unroll
        for (int ks = 0; ks < 8; ks++) {
            uint32_t a[2][4], b[2][4];
#pragma unroll
            for (int mt = 0; mt < 2; mt++)
                lds_x4(a[mt], sbA + off(arow + mt * 16, ks * 2 + ahb));
#pragma unroll
            for (int ntb = 0; ntb < 2; ntb++)
                lds_x4_t(b[ntb], sbE + offE(ks * 16 + btrow, btch_base + ntb * 2));
#pragma unroll
            for (int mt = 0; mt < 2; mt++)
#pragma unroll
                for (int ntb = 0; ntb < 2; ntb++) {
                    mma16816(c[mt][ntb * 2 + 0], a[mt], b[ntb][0], b[ntb][1]);
                    mma16816(c[mt][ntb * 2 + 1], a[mt], b[ntb][2], b[ntb][3]);
                }
        }
        __syncthreads();
        // refill A(st+1) (L2-resident x3h; lands before next wait)
        if (st + 1 < C_NT) {
#pragma unroll
            for (int i = 0; i < 8; i++) {
                int idx = tid + 256 * i, row = idx >> 4, ch = idx & 15;
                cpa16(sbA + off(row, ch), gA3 + (size_t)row * CS + (st + 1) * 128 + ch * 8);
            }
            CP_COMMIT();
        }
    }

    // epilogue: fp32 store out[bh][d][kc]
#pragma unroll
    for (int mt = 0; mt < 2; mt++) {
        const int d0 = wm * 32 + mt * 16 + (lane >> 2);
#pragma unroll
        for (int nt = 0; nt < 4; nt++) {
            const int col = kcbase + wn * 32 + nt * 8 + (lane & 3) * 2;
            float2 v0 = make_float2(c[mt][nt][0], c[mt][nt][1]);
            float2 v1 = make_float2(c[mt][nt][2], c[mt][nt][3]);
            *reinterpret_cast<float2*>(out + ((size_t)(bh * CD + d0)) * CS + col) = v0;
            *reinterpret_cast<float2*>(out + ((size_t)(bh * CD + d0 + 8)) * CS + col) = v1;
        }
    }
}

// ================= launch =================
extern "C" void kernel_launch(void* const* d_in, const int* in_sizes, int n_in,
                              void* d_out, int out_size) {
    (void)in_sizes; (void)n_in; (void)out_size;
    const float* x1   = (const float*)d_in[0];
    const float* x2   = (const float*)d_in[1];
    const float* x3   = (const float*)d_in[2];
    const float* mask = (const float*)d_in[3];
    float* out = (float*)d_out;

    cudaFuncSetAttribute(score_kernel, cudaFuncAttributeMaxDynamicSharedMemorySize, 65792);
    cudaFuncSetAttribute(pv_kernel,    cudaFuncAttributeMaxDynamicSharedMemorySize, 65536);

    convert_kernel<<<(int)((CV_Q + 255) / 256), 256>>>(x2, mask);
    score_kernel<<<C_BH * C_ST, 256, 65792>>>(x1, x3);
    pv_kernel<<<C_BH * C_ST, 256, 65536>>>(out);
}